// round 16
// baseline (speedup 1.0000x reference)
#include <cuda_runtime.h>
#include <cuda_fp16.h>
#include <math.h>
#include <stdint.h>

#define DD 1024
#define BSZ 256

// ---- scratch globals --------------------------------------------------------
__device__ __half g_h16[BSZ * DD];
__device__ float  g_logits[BSZ * DD];
__device__ __half g_pretxt_h[BSZ * DD];
__device__ __half g_pimgb_h[BSZ * DD];
__device__ __half g_rw2_h[DD * DD];    // rw2 fp16 [k][n]
__device__ __half g_aw1_h[DD * DD];
__device__ __half g_aw2_h[DD * DD];
__device__ __half g_rw1_h[2 * DD * DD];
__device__ __half g_text_h[BSZ * DD];
__device__ __half g_img_h[BSZ * DD];

// ---- cp.async helpers ------------------------------------------------------
#define CP_ASYNC16(dst, src) \
    asm volatile("cp.async.cg.shared.global [%0], [%1], 16;" \
        :: "r"(dst), "l"(src) : "memory")
#define CP_COMMIT() asm volatile("cp.async.commit_group;" ::: "memory")
#define CP_WAIT0()  asm volatile("cp.async.wait_group 0;" ::: "memory")
#define CP_WAIT2()  asm volatile("cp.async.wait_group 2;" ::: "memory")

// ---- mma.sync / ldmatrix ----------------------------------------------------
#define LDSM_X4(r0,r1,r2,r3,addr) \
    asm volatile("ldmatrix.sync.aligned.m8n8.x4.shared.b16 {%0,%1,%2,%3}, [%4];" \
        : "=r"(r0),"=r"(r1),"=r"(r2),"=r"(r3) : "r"(addr))
#define LDSM_X4_T(r0,r1,r2,r3,addr) \
    asm volatile("ldmatrix.sync.aligned.m8n8.x4.trans.shared.b16 {%0,%1,%2,%3}, [%4];" \
        : "=r"(r0),"=r"(r1),"=r"(r2),"=r"(r3) : "r"(addr))
#define MMA_F16F32(d0,d1,d2,d3,a0,a1,a2,a3,b0,b1) \
    asm volatile("mma.sync.aligned.m16n8k16.row.col.f32.f16.f16.f32 " \
        "{%0,%1,%2,%3}, {%4,%5,%6,%7}, {%8,%9}, {%0,%1,%2,%3};" \
        : "+f"(d0),"+f"(d1),"+f"(d2),"+f"(d3) \
        : "r"(a0),"r"(a1),"r"(a2),"r"(a3),"r"(b0),"r"(b1))

// ============================================================================
// Prepass: convert all fp32 operands to fp16 (one launch, fully parallel).
// ============================================================================
__global__ void __launch_bounds__(256)
conv_all(const float* __restrict__ aw1, const float* __restrict__ aw2,
         const float* __restrict__ rw1, const float* __restrict__ rw2,
         const float* __restrict__ text, const float* __restrict__ image,
         __half* __restrict__ aw1h, __half* __restrict__ aw2h,
         __half* __restrict__ rw1h, __half* __restrict__ rw2h,
         __half* __restrict__ texth, __half* __restrict__ imgh)
{
    const int b = blockIdx.x;
    const float* src; __half* dst; int off;
    if      (b < 1024) { src = aw1;   dst = aw1h;  off = b; }
    else if (b < 2048) { src = aw2;   dst = aw2h;  off = b - 1024; }
    else if (b < 4096) { src = rw1;   dst = rw1h;  off = b - 2048; }
    else if (b < 5120) { src = rw2;   dst = rw2h;  off = b - 4096; }
    else if (b < 5376) { src = text;  dst = texth; off = b - 5120; }
    else               { src = image; dst = imgh;  off = b - 5376; }
    const int idx = off * 1024 + threadIdx.x * 4;
    float4 v = *(const float4*)(src + idx);
    __half2 h0 = __floats2half2_rn(v.x, v.y);
    __half2 h1 = __floats2half2_rn(v.z, v.w);
    uint2 o; o.x = *(uint32_t*)&h0; o.y = *(uint32_t*)&h1;
    *(uint2*)(dst + idx) = o;
}

// ============================================================================
// Small-chain GEMMs: all-fp16, 4-stage cp.async pipeline, 32x64 CTA tile.
// (validated round-13 structure)
// ============================================================================
template <bool RELU, bool HAS_BIAS, bool HALFOUT>
__device__ __forceinline__ void hgemm_ms(
    const __half* __restrict__ A, const __half* __restrict__ B,
    const float* __restrict__ bias, void* __restrict__ Cv)
{
    __shared__ __half As[4][32][40];
    __shared__ __half Bs[4][32][72];

    const int t    = threadIdx.x;
    const int lane = t & 31;
    const int warp = t >> 5;
    const int m0 = blockIdx.y * 32;
    const int n0 = blockIdx.x * 64;

    const int wm = (warp >> 1) * 16;
    const int wn = (warp & 1) * 32;

    const int ar = t >> 2;
    const int ac = (t & 3) * 8;
    const int br = t >> 2;
    const int bc = (t & 3) * 16;

    const __half* Arow = A + (size_t)(m0 + ar) * DD + ac;
    const __half* Brow = B + (size_t)br * DD + n0 + bc;

    const uint32_t adst0 = (uint32_t)__cvta_generic_to_shared(&As[0][ar][ac]);
    const uint32_t bdst0 = (uint32_t)__cvta_generic_to_shared(&Bs[0][br][bc]);

    const uint32_t aBase = (uint32_t)__cvta_generic_to_shared(
        &As[0][wm + ((lane >> 3) & 1) * 8 + (lane & 7)][(lane >> 4) * 8]);
    const uint32_t bBase = (uint32_t)__cvta_generic_to_shared(
        &Bs[0][((lane >> 3) & 1) * 8 + (lane & 7)][wn + (lane >> 4) * 8]);

    float acc[4][4] = {};

    #pragma unroll
    for (int q = 0; q < 3; q++) {
        const uint32_t ad = adst0 + q * 2560;
        const uint32_t bd = bdst0 + q * 4608;
        const __half* as = Arow + q * 32;
        const __half* bs = Brow + (size_t)(q * 32) * DD;
        CP_ASYNC16(ad, as);
        CP_ASYNC16(bd,      bs);
        CP_ASYNC16(bd + 16, bs + 8);
        CP_COMMIT();
    }

    for (int c = 0; c < 32; c++) {
        CP_WAIT2();
        __syncthreads();

        if (c < 29) {
            const int q = c + 3;
            const uint32_t ad = adst0 + (q & 3) * 2560;
            const uint32_t bd = bdst0 + (q & 3) * 4608;
            const __half* as = Arow + q * 32;
            const __half* bs = Brow + (size_t)(q * 32) * DD;
            CP_ASYNC16(ad, as);
            CP_ASYNC16(bd,      bs);
            CP_ASYNC16(bd + 16, bs + 8);
        }
        CP_COMMIT();

        const uint32_t aB = aBase + (c & 3) * 2560;
        const uint32_t bB = bBase + (c & 3) * 4608;
        #pragma unroll
        for (int ks = 0; ks < 2; ks++) {
            const int kk = ks * 16;
            unsigned a[4];
            LDSM_X4(a[0], a[1], a[2], a[3], aB + kk * 2);
            unsigned b[4][2];
            #pragma unroll
            for (int bt = 0; bt < 2; bt++)
                LDSM_X4_T(b[bt*2][0], b[bt*2][1], b[bt*2+1][0], b[bt*2+1][1],
                          bB + kk * 144 + bt * 32);
            #pragma unroll
            for (int nt = 0; nt < 4; nt++)
                MMA_F16F32(acc[nt][0], acc[nt][1], acc[nt][2], acc[nt][3],
                           a[0], a[1], a[2], a[3], b[nt][0], b[nt][1]);
        }
    }

    const int rbase = wm + (lane >> 2);
    #pragma unroll
    for (int half = 0; half < 2; half++) {
        const int r = m0 + rbase + half * 8;
        #pragma unroll
        for (int nt = 0; nt < 4; nt++) {
            const int col = n0 + wn + nt * 8 + (lane & 3) * 2;
            float v0 = acc[nt][half * 2 + 0];
            float v1 = acc[nt][half * 2 + 1];
            if (HAS_BIAS) { v0 += bias[col]; v1 += bias[col + 1]; }
            if (RELU) { v0 = fmaxf(v0, 0.0f); v1 = fmaxf(v1, 0.0f); }
            if (HALFOUT) {
                __half2 h = __floats2half2_rn(v0, v1);
                *(uint32_t*)((__half*)Cv + (size_t)r * DD + col) = *(uint32_t*)&h;
            } else {
                float2 f = make_float2(v0, v1);
                *(float2*)((float*)Cv + (size_t)r * DD + col) = f;
            }
        }
    }
}

__global__ void __launch_bounds__(128)
small_pair(const __half* __restrict__ text16, const __half* __restrict__ aw1h,
           const float* __restrict__ ab1, __half* __restrict__ h16,
           const __half* __restrict__ img16, const __half* __restrict__ rw1h,
           const float* __restrict__ rb1, __half* __restrict__ pimgb)
{
    if (blockIdx.z == 0)
        hgemm_ms<true, true, true>(text16, aw1h, ab1, h16);
    else
        hgemm_ms<false, true, true>(img16, rw1h, rb1, pimgb);
}

__global__ void __launch_bounds__(128)
small_logits(const __half* __restrict__ h16, const __half* __restrict__ aw2h,
             const float* __restrict__ ab2, float* __restrict__ logits)
{
    hgemm_ms<false, true, false>(h16, aw2h, ab2, logits);
}

// ============================================================================
// FUSED pretxt: per-CTA softmax (phase 1) + GEMM with A from SMEM (phase 2).
//   pretxt[m, n] = (text[m,:] * softmax(logits[m,:])) @ rw1b[:, n]
// Grid (16, 8): 16 n-tiles of 64, 8 m-groups of 32 rows. 128 threads.
// Phase 1: warp w handles rows 8w..8w+7; 32 logits/lane in regs, shuffle
//   reductions; text2 tile written to SMEM fp16, row stride 1032 elems
//   (2064 B; 2064 mod 128 = 16 -> ldmatrix conflict-free across 8 rows).
// Phase 2: B-only 4-stage cp.async pipeline; A ldmatrix directly from T2.
// Dynamic SMEM: T2 32x1032x2 = 66048 B + B stages 4x4608 = 18432 B -> 84480 B.
// ============================================================================
#define PTX_SMEM 84480

__global__ void __launch_bounds__(128)
small_pretxt_fused(const float* __restrict__ logits,
                   const float* __restrict__ text,
                   const __half* __restrict__ rw1bh,
                   __half* __restrict__ pretxt)
{
    extern __shared__ __align__(16) char dsm[];
    __half* T2 = (__half*)dsm;                   // [32][1032]
    __half* Bs = (__half*)(dsm + 66048);         // [4][32][72]

    const int t    = threadIdx.x;
    const int lane = t & 31;
    const int warp = t >> 5;
    const int m0 = blockIdx.y * 32;
    const int n0 = blockIdx.x * 64;

    // ---------------- phase 1: softmax * text into T2 ----------------
    for (int r = warp * 8; r < warp * 8 + 8; r++) {
        const float* lrow = logits + (size_t)(m0 + r) * DD;
        const float* trow = text   + (size_t)(m0 + r) * DD;
        float lv[32];
        #pragma unroll
        for (int q = 0; q < 32; q++) lv[q] = lrow[q * 32 + lane];
        float mx = lv[0];
        #pragma unroll
        for (int q = 1; q < 32; q++) mx = fmaxf(mx, lv[q]);
        #pragma unroll
        for (int o = 16; o > 0; o >>= 1)
            mx = fmaxf(mx, __shfl_xor_sync(0xffffffffu, mx, o));
        float s = 0.0f;
        #pragma unroll
        for (int q = 0; q < 32; q++) { lv[q] = expf(lv[q] - mx); s += lv[q]; }
        #pragma unroll
        for (int o = 16; o > 0; o >>= 1)
            s += __shfl_xor_sync(0xffffffffu, s, o);
        const float inv = 1.0f / s;
        __half* t2row = T2 + r * 1032;
        #pragma unroll
        for (int q = 0; q < 32; q++) {
            const int k = q * 32 + lane;
            t2row[k] = __float2half(trow[k] * (lv[q] * inv));
        }
    }

    // ---------------- phase 2: pretxt tile = T2 @ rw1b ----------------
    const int wm = (warp >> 1) * 16;
    const int wn = (warp & 1) * 32;

    const int br = t >> 2;
    const int bc = (t & 3) * 16;
    const __half* Brow = rw1bh + (size_t)br * DD + n0 + bc;

    const uint32_t bdst0 = (uint32_t)__cvta_generic_to_shared(
        Bs + br * 72 + bc);
    const uint32_t bBase = (uint32_t)__cvta_generic_to_shared(
        Bs + (((lane >> 3) & 1) * 8 + (lane & 7)) * 72 + wn + (lane >> 4) * 8);
    const uint32_t aBase = (uint32_t)__cvta_generic_to_shared(
        T2 + (wm + ((lane >> 3) & 1) * 8 + (lane & 7)) * 1032 + (lane >> 4) * 8);

    float acc[4][4] = {};

    // B prologue (phase-1 work above covers load latency of these too)
    #pragma unroll
    for (int q = 0; q < 3; q++) {
        const uint32_t bd = bdst0 + q * 4608;
        const __half* bs = Brow + (size_t)(q * 32) * DD;
        CP_ASYNC16(bd,      bs);
        CP_ASYNC16(bd + 16, bs + 8);
        CP_COMMIT();
    }
    __syncthreads();   // T2 complete before any warp ldmatrix's it

    for (int c = 0; c < 32; c++) {
        CP_WAIT2();
        __syncthreads();

        if (c < 29) {
            const int q = c + 3;
            const uint32_t bd = bdst0 + (q & 3) * 4608;
            const __half* bs = Brow + (size_t)(q * 32) * DD;
            CP_ASYNC16(bd,      bs);
            CP_ASYNC16(bd + 16, bs + 8);
        }
        CP_COMMIT();

        const uint32_t aB = aBase + c * 64;          // 32 k * 2B per chunk
        const uint32_t bB = bBase + (c & 3) * 4608;
        #pragma unroll
        for (int ks = 0; ks < 2; ks++) {
            const int kk = ks * 16;
            unsigned a[4];
            LDSM_X4(a[0], a[1], a[2], a[3], aB + kk * 2);
            unsigned b[4][2];
            #pragma unroll
            for (int bt = 0; bt < 2; bt++)
                LDSM_X4_T(b[bt*2][0], b[bt*2][1], b[bt*2+1][0], b[bt*2+1][1],
                          bB + kk * 144 + bt * 32);
            #pragma unroll
            for (int nt = 0; nt < 4; nt++)
                MMA_F16F32(acc[nt][0], acc[nt][1], acc[nt][2], acc[nt][3],
                           a[0], a[1], a[2], a[3], b[nt][0], b[nt][1]);
        }
    }

    const int rbase = wm + (lane >> 2);
    #pragma unroll
    for (int half = 0; half < 2; half++) {
        const int r = m0 + rbase + half * 8;
        #pragma unroll
        for (int nt = 0; nt < 4; nt++) {
            const int col = n0 + wn + nt * 8 + (lane & 3) * 2;
            __half2 h = __floats2half2_rn(acc[nt][half * 2 + 0],
                                          acc[nt][half * 2 + 1]);
            *(uint32_t*)(pretxt + (size_t)r * DD + col) = *(uint32_t*)&h;
        }
    }
}

// ============================================================================
// Big GEMM on mma.sync (fp16 in, fp32 accum) — at the sm_103 register-MMA
// issue floor (validated): CTA 128x128, BK=32, 8 warps (2m x 4n),
// warp tile 64x32, 2 CTAs/SM, double-buffered, cp.async for B,
// SMEM-side relu(pretxt+pimgb) A synthesis.
// ============================================================================
__device__ __forceinline__ uint4 fuse_relu_f16(uint4 p, uint4 t)
{
    const __half2 z = __float2half2_rn(0.0f);
    uint4 r;
    const __half2* pp = (const __half2*)&p;
    const __half2* tt = (const __half2*)&t;
    __half2* rr = (__half2*)&r;
    #pragma unroll
    for (int q = 0; q < 4; q++)
        rr[q] = __hmax2(__hadd2(pp[q], tt[q]), z);
    return r;
}

__global__ void __launch_bounds__(256, 2)
big_gemm_mma(const __half* __restrict__ pretxt,
             const __half* __restrict__ pimgb,
             const __half* __restrict__ rw2,
             const float* __restrict__ image,
             const float* __restrict__ rb2,
             float* __restrict__ out)
{
    __shared__ __half As[2][128][40];
    __shared__ __half Bs[2][32][136];

    const uint32_t ASTG = 128 * 40 * 2;
    const uint32_t BSTG = 32 * 136 * 2;

    const int t    = threadIdx.x;
    const int lane = t & 31;
    const int warp = t >> 5;
    const int n0 = blockIdx.x * 128;
    const int m0 = blockIdx.y * 128;
    const int i  = m0 >> 8;
    const int j0 = m0 & 255;

    const int wm = (warp >> 2) * 64;
    const int wn = (warp & 3) * 32;

    const int ar  = t >> 1;
    const int akv = (t & 1) * 16;
    const int br  = t >> 3;
    const int bnv = (t & 7) * 16;

    const __half* ptrow = pretxt + (size_t)i * DD;
    const __half* parow = pimgb + (size_t)(j0 + ar) * DD + akv;
    const __half* pbrow = rw2 + (size_t)br * DD + n0 + bnv;

    const uint32_t bdst0 = (uint32_t)__cvta_generic_to_shared(&Bs[0][br][bnv]);

    const uint32_t aBase = (uint32_t)__cvta_generic_to_shared(
        &As[0][wm + ((lane >> 3) & 1) * 8 + (lane & 7)][(lane >> 4) * 8]);
    const uint32_t bBase = (uint32_t)__cvta_generic_to_shared(
        &Bs[0][((lane >> 3) & 1) * 8 + (lane & 7)][wn + (lane >> 4) * 8]);

    float acc[4][4][4] = {};

    CP_ASYNC16(bdst0,      pbrow);
    CP_ASYNC16(bdst0 + 16, pbrow + 8);
    CP_COMMIT();
    {
        uint4 pv0 = *(const uint4*)(parow);
        uint4 pv1 = *(const uint4*)(parow + 8);
        uint4 tv0 = *(const uint4*)(ptrow + akv);
        uint4 tv1 = *(const uint4*)(ptrow + akv + 8);
        *(uint4*)(&As[0][ar][akv])     = fuse_relu_f16(pv0, tv0);
        *(uint4*)(&As[0][ar][akv + 8]) = fuse_relu_f16(pv1, tv1);
    }
    CP_WAIT0();
    __syncthreads();

    uint4 pv0, pv1, tv0, tv1;
    for (int c = 0; c < 32; c++) {
        const int s  = c & 1;
        const int ns = s ^ 1;
        const int kn = (c + 1) * 32;

        if (c < 31) {
            CP_ASYNC16(bdst0 + ns * BSTG,      pbrow + (size_t)kn * DD);
            CP_ASYNC16(bdst0 + ns * BSTG + 16, pbrow + (size_t)kn * DD + 8);
            CP_COMMIT();
            pv0 = *(const uint4*)(parow + kn);
            pv1 = *(const uint4*)(parow + kn + 8);
            tv0 = *(const uint4*)(ptrow + kn + akv);
            tv1 = *(const uint4*)(ptrow + kn + akv + 8);
        }

        const uint32_t aB = aBase + s * ASTG;
        const uint32_t bB = bBase + s * BSTG;
        #pragma unroll
        for (int ks = 0; ks < 2; ks++) {
            const int kk = ks * 16;
            unsigned a[4][4];
            #pragma unroll
            for (int mt = 0; mt < 4; mt++)
                LDSM_X4(a[mt][0], a[mt][1], a[mt][2], a[mt][3],
                        aB + mt * 16 * 80 + kk * 2);
            unsigned b[4][2];
            #pragma unroll
            for (int bt = 0; bt < 2; bt++)
                LDSM_X4_T(b[bt*2][0], b[bt*2][1], b[bt*2+1][0], b[bt*2+1][1],
                          bB + kk * 272 + bt * 32);
            #pragma unroll
            for (int mt = 0; mt < 4; mt++)
                #pragma unroll
                for (int nt = 0; nt < 4; nt++)
                    MMA_F16F32(acc[mt][nt][0], acc[mt][nt][1],
                               acc[mt][nt][2], acc[mt][nt][3],
                               a[mt][0], a[mt][1], a[mt][2], a[mt][3],
                               b[nt][0], b[nt][1]);
        }

        if (c < 31) {
            *(uint4*)(&As[ns][ar][akv])     = fuse_relu_f16(pv0, tv0);
            *(uint4*)(&As[ns][ar][akv + 8]) = fuse_relu_f16(pv1, tv1);
            CP_WAIT0();
        }
        __syncthreads();
    }

    #pragma unroll
    for (int mt = 0; mt < 4; mt++) {
        const int rbase = wm + mt * 16 + (lane >> 2);
        #pragma unroll
        for (int half = 0; half < 2; half++) {
            const int r = rbase + half * 8;
            const float* img = image + (size_t)(j0 + r) * DD;
            const size_t orow = (size_t)(m0 + r) * DD;
            #pragma unroll
            for (int nt = 0; nt < 4; nt++) {
                const int col = n0 + wn + nt * 8 + (lane & 3) * 2;
                float2 im = *(const float2*)(img + col);
                float2 rb = *(const float2*)(rb2 + col);
                float2 o;
                o.x = acc[mt][nt][half * 2 + 0] + im.x + rb.x;
                o.y = acc[mt][nt][half * 2 + 1] + im.y + rb.y;
                *(float2*)(out + orow + col) = o;
            }
        }
    }
}

// ---------------------------------------------------------------------------
extern "C" void kernel_launch(void* const* d_in, const int* in_sizes, int n_in,
                              void* d_out, int out_size)
{
    const float* image = (const float*)d_in[0];
    const float* text  = (const float*)d_in[1];
    const float* aw1   = (const float*)d_in[2];
    const float* ab1   = (const float*)d_in[3];
    const float* aw2   = (const float*)d_in[4];
    const float* ab2   = (const float*)d_in[5];
    const float* rw1   = (const float*)d_in[6];
    const float* rb1   = (const float*)d_in[7];
    const float* rw2   = (const float*)d_in[8];
    const float* rb2   = (const float*)d_in[9];
    float* out = (float*)d_out;

    __half *h16_p, *pretxt_p, *pimgb_p, *rw2h_p;
    __half *aw1h_p, *aw2h_p, *rw1h_p, *texth_p, *imgh_p;
    float *logits_p;
    cudaGetSymbolAddress((void**)&h16_p,    g_h16);
    cudaGetSymbolAddress((void**)&logits_p, g_logits);
    cudaGetSymbolAddress((void**)&pretxt_p, g_pretxt_h);
    cudaGetSymbolAddress((void**)&pimgb_p,  g_pimgb_h);
    cudaGetSymbolAddress((void**)&rw2h_p,   g_rw2_h);
    cudaGetSymbolAddress((void**)&aw1h_p,   g_aw1_h);
    cudaGetSymbolAddress((void**)&aw2h_p,   g_aw2_h);
    cudaGetSymbolAddress((void**)&rw1h_p,   g_rw1_h);
    cudaGetSymbolAddress((void**)&texth_p,  g_text_h);
    cudaGetSymbolAddress((void**)&imgh_p,   g_img_h);

    // Host-side attr set; deterministic & idempotent.
    cudaFuncSetAttribute(small_pretxt_fused,
                         cudaFuncAttributeMaxDynamicSharedMemorySize, PTX_SMEM);

    dim3 blk128(128);
    dim3 gsmall(16, 8);   // 32x64 tiles over [256 x 1024] -> 128 CTAs

    // prepass: convert all fp32 operands to fp16 (one launch)
    conv_all<<<5632, 256>>>(aw1, aw2, rw1, rw2, text, image,
                            aw1h_p, aw2h_p, rw1h_p, rw2h_p, texth_p, imgh_p);
    // z=0: h16 = relu(text@aw1+ab1); z=1: pimgb = image@rw1[:D]+rb1
    small_pair<<<dim3(16, 8, 2), blk128>>>(
        texth_p, aw1h_p, ab1, h16_p, imgh_p, rw1h_p, rb1, pimgb_p);
    // logits = h @ aw2 + ab2   (fp32 out for softmax)
    small_logits<<<gsmall, blk128>>>(h16_p, aw2h_p, ab2, logits_p);
    // pretxt = fp16((text * softmax(logits)) @ rw1[D:])   [fused]
    small_pretxt_fused<<<gsmall, blk128, PTX_SMEM>>>(
        logits_p, text, rw1h_p + (size_t)DD * DD, pretxt_p);
    // big fused GEMM (at register-HMMA floor)
    big_gemm_mma<<<dim3(8, 512), 256>>>(
        pretxt_p, pimgb_p, rw2h_p, image, rb2, out);
}